// round 6
// baseline (speedup 1.0000x reference)
#include <cuda_runtime.h>
#include <math.h>

#define NSPEC  256
#define NSPEC3 5456
#define NPACK  2856   // sum over l of (2l+1)*(l+1)  — only nloc >= l kept

// scratch (static device globals — allowed)
__device__ float2 g_fhat [16*16*NSPEC];     // [b][f][s]
__device__ float2 g_psi  [16*64*NSPEC];     // [i][o][s]
__device__ float2 g_Fz   [1024*NPACK];      // [b*64+o][packed e]  (23.4 MB)
__device__ float  g_wig3p[32*NPACK];        // packed wig_so3

__constant__ int c_offs[16] = {0,1,10,35,84,165,286,455,680,969,1330,1771,2300,2925,3654,4495};
__constant__ int c_offP[16] = {0,1,7,22,50,95,161,252,372,525,715,946,1222,1547,1925,2360};

// compile-time twiddles: TWC[j] = cos(2*pi*j/32), TWS[j] = sin(2*pi*j/32)
__device__ constexpr float TWC[32] = {
 1.0f, 0.9807852804f, 0.9238795325f, 0.8314696123f, 0.7071067812f, 0.5555702330f, 0.3826834324f, 0.1950903220f,
 0.0f,-0.1950903220f,-0.3826834324f,-0.5555702330f,-0.7071067812f,-0.8314696123f,-0.9238795325f,-0.9807852804f,
-1.0f,-0.9807852804f,-0.9238795325f,-0.8314696123f,-0.7071067812f,-0.5555702330f,-0.3826834324f,-0.1950903220f,
 0.0f, 0.1950903220f, 0.3826834324f, 0.5555702330f, 0.7071067812f, 0.8314696123f, 0.9238795325f, 0.9807852804f };
__device__ constexpr float TWS[32] = {
 0.0f, 0.1950903220f, 0.3826834324f, 0.5555702330f, 0.7071067812f, 0.8314696123f, 0.9238795325f, 0.9807852804f,
 1.0f, 0.9807852804f, 0.9238795325f, 0.8314696123f, 0.7071067812f, 0.5555702330f, 0.3826834324f, 0.1950903220f,
 0.0f,-0.1950903220f,-0.3826834324f,-0.5555702330f,-0.7071067812f,-0.8314696123f,-0.9238795325f,-0.9807852804f,
-1.0f,-0.9807852804f,-0.9238795325f,-0.8314696123f,-0.7071067812f,-0.5555702330f,-0.3826834324f,-0.1950903220f };

// ---------------- Kernel 1: fhat[b,f,s] = sum_j wig_s2[j,s] * DFT_alpha(x)[b,f,j,m(s)] ----------------
__global__ void k_fhat(const float* __restrict__ x, const float* __restrict__ wig) {
    __shared__ float  sx[64*65];
    __shared__ float2 xf[64*31];       // [j][mt], mt = m+15
    __shared__ float  c64[64], s64[64];
    int b = blockIdx.x, f = blockIdx.y, tid = threadIdx.x;
    if (tid < 64) { float sv, cv; sincospif((float)tid/32.0f, &sv, &cv); c64[tid]=cv; s64[tid]=sv; }
    const float* xp = x + (size_t)(b*16+f)*4096;
    for (int p = tid; p < 4096; p += 256) sx[(p>>6)*65 + (p&63)] = xp[p];
    __syncthreads();
    for (int p = tid; p < 1984; p += 256) {           // 31 m-values x 64 betas
        int mt = p >> 6, j = p & 63, m = mt - 15;
        float ar=0.f, ai=0.f;
        const float* row = &sx[j*65];
        #pragma unroll 8
        for (int a = 0; a < 64; a++) {
            int t = (m*a) & 63;
            float v = row[a];
            ar += v*c64[t];                            // e^{-2pi i m a/64}
            ai -= v*s64[t];
        }
        xf[j*31+mt] = make_float2(ar, ai);
    }
    __syncthreads();
    int s = tid;
    int l = (int)sqrtf((float)s);
    while ((l+1)*(l+1) <= s) ++l;
    while (l*l > s) --l;
    int mt = s - l*l - l + 15;
    float ar=0.f, ai=0.f;
    #pragma unroll 8
    for (int j = 0; j < 64; j++) {
        float w = wig[j*NSPEC + s];
        float2 v = xf[j*31+mt];
        ar += w*v.x; ai += w*v.y;
    }
    g_fhat[(b*16+f)*NSPEC + s] = make_float2(ar, ai);
}

// ---------------- Kernel 2: psi[i,o,s] = scaling * sum_g kernel[i,o,g] * Fk[s,g] ----------------
__global__ void k_psi(const float* __restrict__ kern, const float* __restrict__ fkr,
                      const float* __restrict__ fki, float scaling) {
    __shared__ float2 fk[32];
    int s = blockIdx.x, tid = threadIdx.x;
    if (tid < 32) fk[tid] = make_float2(fkr[s*32+tid]*scaling, fki[s*32+tid]*scaling);
    __syncthreads();
    for (int p = tid; p < 1024; p += 256) {            // p = i*64+o
        const float* kp = kern + p*32;
        float ar=0.f, ai=0.f;
        #pragma unroll
        for (int g = 0; g < 32; g++) { float kv = kp[g]; ar += kv*fk[g].x; ai += kv*fk[g].y; }
        g_psi[p*NSPEC + s] = make_float2(ar, ai);
    }
}

// ---------------- Kernel 2b: pack wig_so3 to nloc>=l layout ----------------
__global__ void k_pack(const float* __restrict__ wig3) {
    int k = blockIdx.x, tid = threadIdx.x;
    for (int p = tid; p < NPACK; p += 256) {
        int l = 15;
        while (c_offP[l] > p) --l;
        int r = p - c_offP[l];
        int mloc = r / (l+1);
        int nq   = r - mloc*(l+1);
        g_wig3p[k*NPACK + p] = wig3[k*NSPEC3 + c_offs[l] + mloc*(2*l+1) + (nq + l)];
    }
}

// ---------------- Kernel 3: packed Fz (only n >= 0), conflict-free [i][s] smem layout ----------------
__global__ void k_fz() {
    extern __shared__ float2 sm3[];
    float2* fh = sm3;          // [i*256+s]
    float2* ps = sm3 + 4096;   // [i*256+s]
    int bo = blockIdx.x, b = bo >> 6, o = bo & 63, tid = threadIdx.x;
    for (int p = tid; p < 4096; p += 512) {
        int i = p >> 8, s = p & 255;
        fh[p] = g_fhat[(b*16+i)*NSPEC + s];            // coalesced
        ps[p] = g_psi [(i*64+o)*NSPEC + s];            // coalesced
    }
    __syncthreads();
    for (int e = tid; e < NPACK; e += 512) {
        int l = 15;
        while (c_offP[l] > e) --l;
        int r = e - c_offP[l];
        int mloc = r / (l+1);
        int nq   = r - mloc*(l+1);
        int sm_ = l*l + mloc;
        int sn  = l*l + nq + l;
        float ar=0.f, ai=0.f;
        #pragma unroll
        for (int i = 0; i < 16; i++) {
            float2 a = fh[i*256 + sm_];
            float2 c = ps[i*256 + sn];
            ar += a.x*c.x + a.y*c.y;                   // fhat * conj(psi)
            ai += a.y*c.x - a.x*c.y;
        }
        g_Fz[(size_t)bo*NPACK + e] = make_float2(ar, ai);
    }
}

// ---------------- stage-1 core: compile-time twiddles (FFMA-imm) ----------------
template<int A0>
__device__ __forceinline__ void stage1_core(const float2* __restrict__ spcp,
                                            float2* __restrict__ V, int n) {
    float s0r=0,s0i=0,s1r=0,s1i=0,s2r=0,s2i=0,s3r=0,s3i=0;
    #pragma unroll
    for (int mi = 0; mi < 31; mi++) {
        const int j = ((mi - 15) * A0) & 31;           // mod 32 (two's complement ok)
        const float c = TWC[j], s = TWS[j];
        float2 sp = spcp[mi*16 + n];
        float tr = sp.x*c - sp.y*s;
        float ti = sp.x*s + sp.y*c;
        const int r = (mi + 1) & 3;                    // (mi-15) mod 4
        if      (r == 0) { s0r += tr; s0i += ti; }
        else if (r == 1) { s1r += tr; s1i += ti; }
        else if (r == 2) { s2r += tr; s2i += ti; }
        else             { s3r += tr; s3i += ti; }
    }
    V[(A0     )*16 + n] = make_float2(s0r + s1r + s2r + s3r,  s0i + s1i + s2i + s3i);
    V[(A0 +  8)*16 + n] = make_float2(s0r - s1i - s2r + s3i,  s0i + s1r - s2i - s3r);
    V[(A0 + 16)*16 + n] = make_float2(s0r - s1r + s2r - s3r,  s0i - s1i + s2i - s3i);
    V[(A0 + 24)*16 + n] = make_float2(s0r + s1i - s2r - s3i,  s0i - s1r - s2i + s3r);
}

// ---------------- Kernel 4 (fused, Hermitian + radix-4 imm-twiddle, dual-k) ----------------
// grid (1024 bo, 4 kq); each block handles 8 beta_out values, 2 at a time.
// smem float2 units: Fz 2856 | spc 1024 (2x512) | Vv 1024 (2x512) | cs16 496
// total = (2856+1024+1024+496)*8 = 43200 B -> 5 CTAs/SM
__global__ void k_main(const float* __restrict__ bias, float* __restrict__ out) {
    extern __shared__ float smraw[];
    float2* Fz   = (float2*)smraw;     // 2856
    float2* spc  = Fz  + 2856;         // 1024: [kp*512 + mi*16 + nq]
    float2* Vv   = spc + 1024;         // 1024: [kp*512 + a*16 + nq]
    float2* cs16 = Vv  + 1024;         // 496:  cs16[q*16+r] = e^{+2pi i (q-15) r/32}, r<16
    int tid = threadIdx.x;
    int bo = blockIdx.x, o = bo & 63;
    int kq = blockIdx.y;

    for (int p = tid; p < 496; p += 256) {
        int q = p >> 4, r = p & 15;
        int t = ((q-15)*r) & 31;
        float sv, cv; sincospif((float)t / 16.0f, &sv, &cv);
        cs16[p] = make_float2(cv, sv);
    }
    for (int p = tid; p < NPACK; p += 256) Fz[p] = g_Fz[(size_t)bo*NPACK + p];
    float bv = bias[o];

    int kp = tid >> 7, t2 = tid & 127;                 // spec & stage2 mapping
    int w = tid >> 5, lane = tid & 31;                 // stage1 mapping
    int s1kp = lane >> 4, s1n = lane & 15;

    for (int kk4 = 0; kk4 < 4; kk4++) {
        int k = kq*8 + kk4*2 + kp;
        __syncthreads();                               // prior stage2 done before spc/Vv rewrite

        // spec[m,n] for n>=0 (half-block per k-plane)
        const float* wkg = g_wig3p + k*NPACK;
        for (int p = t2; p < 496; p += 128) {
            int mi = p >> 4, nq = p & 15;
            int m = mi - 15;
            int am = m < 0 ? -m : m;
            int lmin = am > nq ? am : nq;
            float ar = 0.f, ai = 0.f;
            for (int l = lmin; l < 16; l++) {
                int idx = c_offP[l] + (m+l)*(l+1) + nq;
                float d = __ldg(&wkg[idx]);
                float2 fz = Fz[idx];
                ar += fz.x*d;
                ai += fz.y*d;
            }
            spc[kp*512 + p] = make_float2(ar, ai);
        }
        __syncthreads();

        // stage 1 (radix-4 over m, warp-uniform a0 = warp id, imm twiddles)
        {
            const float2* spp = spc + s1kp*512;
            float2* V = Vv + s1kp*512;
            switch (w) {
                case 0: stage1_core<0>(spp, V, s1n); break;
                case 1: stage1_core<1>(spp, V, s1n); break;
                case 2: stage1_core<2>(spp, V, s1n); break;
                case 3: stage1_core<3>(spp, V, s1n); break;
                case 4: stage1_core<4>(spp, V, s1n); break;
                case 5: stage1_core<5>(spp, V, s1n); break;
                case 6: stage1_core<6>(spp, V, s1n); break;
                case 7: stage1_core<7>(spp, V, s1n); break;
            }
        }
        __syncthreads();

        // stage 2 (radix-2 over n): out[a][g], out[a][g+16]; 4 a-values per thread
        {
            int hi = t2 >> 4, lo = t2 & 15;            // hi in 0..7, g = lo
            const float2* V = Vv + kp*512;
            size_t base = ((size_t)bo*32 + k)*1024;
            #pragma unroll
            for (int da = 0; da < 4; da++) {
                int a = hi*4 + da;
                float se = 0.f, so = 0.f;
                #pragma unroll
                for (int n = 1; n < 16; n++) {
                    float2 v = V[a*16 + n];            // broadcast
                    float2 e = cs16[(n+15)*16 + lo];   // e^{+2pi i n g/32}
                    float t = v.x*e.x - v.y*e.y;
                    if (n & 1) so += t; else se += t;
                }
                float c0 = bv + V[a*16].x;
                out[base + a*32 + lo     ] = c0 + 2.f*(se + so);
                out[base + a*32 + lo + 16] = c0 + 2.f*(se - so);
            }
        }
    }
}

extern "C" void kernel_launch(void* const* d_in, const int* in_sizes, int n_in,
                              void* d_out, int out_size) {
    const float* x       = (const float*)d_in[0];
    const float* kern    = (const float*)d_in[1];
    const float* bias    = (const float*)d_in[2];
    const float* wig_s2  = (const float*)d_in[3];
    const float* fk_re   = (const float*)d_in[4];
    const float* fk_im   = (const float*)d_in[5];
    const float* wig_so3 = (const float*)d_in[6];
    float* out = (float*)d_out;

    float scaling = 1.0f / sqrtf(32768.0f);

    cudaFuncSetAttribute(k_fz,   cudaFuncAttributeMaxDynamicSharedMemorySize, 65536);
    cudaFuncSetAttribute(k_main, cudaFuncAttributeMaxDynamicSharedMemorySize, 43200);

    k_fhat<<<dim3(16,16), 256>>>(x, wig_s2);
    k_psi <<<256, 256>>>(kern, fk_re, fk_im, scaling);
    k_pack<<<32, 256>>>(wig_so3);
    k_fz  <<<1024, 512, 65536>>>();
    k_main<<<dim3(1024, 4), 256, 43200>>>(bias, out);
}

// round 7
// speedup vs baseline: 1.1953x; 1.1953x over previous
#include <cuda_runtime.h>
#include <math.h>

#define NSPEC  256
#define NSPEC3 5456
#define NPACK  2856   // sum over l of (2l+1)*(l+1)  — only nloc >= l kept

// scratch (static device globals — allowed)
__device__ float2 g_fhat [16*16*NSPEC];     // [b][f][s]
__device__ float2 g_psi  [16*64*NSPEC];     // [i][o][s]
__device__ float2 g_Fz   [1024*NPACK];      // [b*64+o][packed e]  (23.4 MB)
__device__ float  g_wig3p[32*NPACK];        // packed wig_so3
__device__ int    g_lut  [NPACK];           // packed (sm_ << 16) | sn for k_fz

__constant__ int c_offs[16] = {0,1,10,35,84,165,286,455,680,969,1330,1771,2300,2925,3654,4495};
__constant__ int c_offP[16] = {0,1,7,22,50,95,161,252,372,525,715,946,1222,1547,1925,2360};
// c_step[l] = (2l+3)(l+1): idx_{l+1} = idx_l + c_step[l] + m
__constant__ int c_step[15] = {3,10,21,36,55,78,105,136,171,210,253,300,351,406,465};

// ---------------- Kernel 1: fhat[b,f,s] (Hermitian fold: DFT only for m>=0) ----------------
__global__ void k_fhat(const float* __restrict__ x, const float* __restrict__ wig) {
    __shared__ float  sx[64*65];
    __shared__ float2 xf[64*16];       // [j][m], m = 0..15
    __shared__ float2 cs64[64];        // e^{-2pi i t/64}
    int b = blockIdx.x, f = blockIdx.y, tid = threadIdx.x;
    if (tid < 64) { float sv, cv; sincospif((float)tid/32.0f, &sv, &cv); cs64[tid] = make_float2(cv, -sv); }
    const float* xp = x + (size_t)(b*16+f)*4096;
    for (int p = tid; p < 4096; p += 256) sx[(p>>6)*65 + (p&63)] = xp[p];
    __syncthreads();
    for (int p = tid; p < 1024; p += 256) {           // 16 m-values (0..15) x 64 betas
        int m = p >> 6, j = p & 63;
        float ar=0.f, ai=0.f;
        const float* row = &sx[j*65];
        int t = 0;
        #pragma unroll 8
        for (int a = 0; a < 64; a++) {
            float2 e = cs64[t];                        // broadcast
            float v = row[a];
            ar += v*e.x;
            ai += v*e.y;
            t = (t + m) & 63;
        }
        xf[j*16+m] = make_float2(ar, ai);
    }
    __syncthreads();
    int s = tid;
    int l = (int)sqrtf((float)s);
    while ((l+1)*(l+1) <= s) ++l;
    while (l*l > s) --l;
    int m = s - l*l - l;
    int am = m < 0 ? -m : m;
    float sgn = m < 0 ? -1.f : 1.f;                    // xf[-m] = conj(xf[m])
    float ar=0.f, ai=0.f;
    #pragma unroll 8
    for (int j = 0; j < 64; j++) {
        float w = wig[j*NSPEC + s];
        float2 v = xf[j*16+am];
        ar += w*v.x; ai += w*v.y;
    }
    g_fhat[(b*16+f)*NSPEC + s] = make_float2(ar, sgn*ai);
}

// ---------------- Kernel 2: psi[i,o,s] = scaling * sum_g kernel[i,o,g] * Fk[s,g] ----------------
__global__ void k_psi(const float* __restrict__ kern, const float* __restrict__ fkr,
                      const float* __restrict__ fki, float scaling) {
    __shared__ float2 fk[32];
    int s = blockIdx.x, tid = threadIdx.x;
    if (tid < 32) fk[tid] = make_float2(fkr[s*32+tid]*scaling, fki[s*32+tid]*scaling);
    __syncthreads();
    for (int p = tid; p < 1024; p += 256) {            // p = i*64+o
        const float* kp = kern + p*32;
        float ar=0.f, ai=0.f;
        #pragma unroll
        for (int g = 0; g < 32; g++) { float kv = kp[g]; ar += kv*fk[g].x; ai += kv*fk[g].y; }
        g_psi[p*NSPEC + s] = make_float2(ar, ai);
    }
}

// ---------------- Kernel 2b: pack wig_so3 to nloc>=l layout + build k_fz index LUT ----------------
__global__ void k_pack(const float* __restrict__ wig3) {
    int k = blockIdx.x, tid = threadIdx.x;
    for (int p = tid; p < NPACK; p += 256) {
        int l = 15;
        while (c_offP[l] > p) --l;
        int r = p - c_offP[l];
        int mloc = r / (l+1);
        int nq   = r - mloc*(l+1);
        g_wig3p[k*NPACK + p] = wig3[k*NSPEC3 + c_offs[l] + mloc*(2*l+1) + (nq + l)];
        if (k == 0) {
            int sm_ = l*l + mloc;
            int sn  = l*l + nq + l;
            g_lut[p] = (sm_ << 16) | sn;
        }
    }
}

// ---------------- Kernel 3: packed Fz (only n >= 0), conflict-free [i][s] smem layout ----------------
__global__ void k_fz() {
    extern __shared__ float2 sm3[];
    float2* fh = sm3;          // [i*256+s]
    float2* ps = sm3 + 4096;   // [i*256+s]
    int bo = blockIdx.x, b = bo >> 6, o = bo & 63, tid = threadIdx.x;
    for (int p = tid; p < 4096; p += 512) {
        int i = p >> 8, s = p & 255;
        fh[p] = g_fhat[(b*16+i)*NSPEC + s];            // coalesced
        ps[p] = g_psi [(i*64+o)*NSPEC + s];            // coalesced
    }
    __syncthreads();
    for (int e = tid; e < NPACK; e += 512) {
        int lu = __ldg(&g_lut[e]);
        int sm_ = lu >> 16, sn = lu & 0xffff;
        float ar=0.f, ai=0.f;
        #pragma unroll
        for (int i = 0; i < 16; i++) {
            float2 a = fh[i*256 + sm_];
            float2 c = ps[i*256 + sn];
            ar += a.x*c.x + a.y*c.y;                   // fhat * conj(psi)
            ai += a.y*c.x - a.x*c.y;
        }
        g_Fz[(size_t)bo*NPACK + e] = make_float2(ar, ai);
    }
}

// ---------------- Kernel 4 (fused, Hermitian + radix-4, dual-k): spec(n>=0) + 2D synthesis ----------------
// grid (1024 bo, 4 kq); each block handles 8 beta_out values, 2 at a time.
// smem float2 units: Fz 2856 | spc 1024 (2x512) | Vv 1024 (2x512) | cs16 496
// total = (2856+1024+1024+496)*8 = 43200 B -> 5 CTAs/SM
__global__ void k_main(const float* __restrict__ bias, float* __restrict__ out) {
    extern __shared__ float smraw[];
    float2* Fz   = (float2*)smraw;     // 2856
    float2* spc  = Fz  + 2856;         // 1024: [kp*512 + mi*16 + nq]
    float2* Vv   = spc + 1024;         // 1024: [kp*512 + a*16 + nq]
    float2* cs16 = Vv  + 1024;         // 496:  cs16[q*16+r] = e^{+2pi i (q-15) r/32}, r<16
    int tid = threadIdx.x;
    int bo = blockIdx.x, o = bo & 63;
    int kq = blockIdx.y;

    for (int p = tid; p < 496; p += 256) {
        int q = p >> 4, r = p & 15;
        int t = ((q-15)*r) & 31;
        float sv, cv; sincospif((float)t / 16.0f, &sv, &cv);
        cs16[p] = make_float2(cv, sv);
    }
    for (int p = tid; p < NPACK; p += 256) Fz[p] = g_Fz[(size_t)bo*NPACK + p];
    float bv = bias[o];

    int kp = tid >> 7, t2 = tid & 127;

    for (int kk4 = 0; kk4 < 4; kk4++) {
        int k = kq*8 + kk4*2 + kp;
        __syncthreads();                               // prior stage2 done before spc/Vv rewrite

        // spec[m,n] for n>=0 (half-block per k-plane), incremental packed index
        const float* wkg = g_wig3p + k*NPACK;
        for (int p = t2; p < 496; p += 128) {
            int mi = p >> 4, nq = p & 15;
            int m = mi - 15;
            int am = m < 0 ? -m : m;
            int lmin = am > nq ? am : nq;
            float ar = 0.f, ai = 0.f;
            int idx = c_offP[lmin] + (m+lmin)*(lmin+1) + nq;
            for (int l = lmin; l < 16; l++) {
                float d = __ldg(&wkg[idx]);
                float2 fz = Fz[idx];
                ar += fz.x*d;
                ai += fz.y*d;
                if (l < 15) idx += c_step[l] + m;
            }
            spc[kp*512 + p] = make_float2(ar, ai);
        }
        __syncthreads();

        // stage 1 (radix-4 over m): 31 cmacs -> V[a0], V[a0+8], V[a0+16], V[a0+24]
        {
            int a0 = t2 >> 4, n = t2 & 15;             // a0 in 0..7
            float s0r=0,s0i=0,s1r=0,s1i=0,s2r=0,s2i=0,s3r=0,s3i=0;
            #pragma unroll
            for (int mi = 0; mi < 31; mi++) {
                float2 sp = spc[kp*512 + mi*16 + n];
                float2 e  = cs16[mi*16 + a0];          // e^{+2pi i (mi-15) a0/32}
                float tr = sp.x*e.x - sp.y*e.y;
                float ti = sp.x*e.y + sp.y*e.x;
                int r = (mi + 1) & 3;                  // (mi-15) mod 4
                if      (r == 0) { s0r += tr; s0i += ti; }
                else if (r == 1) { s1r += tr; s1i += ti; }
                else if (r == 2) { s2r += tr; s2i += ti; }
                else             { s3r += tr; s3i += ti; }
            }
            float2* V = Vv + kp*512;
            V[(a0     )*16 + n] = make_float2(s0r + s1r + s2r + s3r,  s0i + s1i + s2i + s3i);
            V[(a0 +  8)*16 + n] = make_float2(s0r - s1i - s2r + s3i,  s0i + s1r - s2i - s3r);
            V[(a0 + 16)*16 + n] = make_float2(s0r - s1r + s2r - s3r,  s0i - s1i + s2i - s3i);
            V[(a0 + 24)*16 + n] = make_float2(s0r + s1i - s2r - s3i,  s0i - s1r - s2i + s3r);
        }
        __syncthreads();

        // stage 2 (radix-2 over n): out[a][g], out[a][g+16]; 4 a-values per thread
        {
            int hi = t2 >> 4, lo = t2 & 15;            // hi in 0..7, g = lo
            const float2* V = Vv + kp*512;
            size_t base = ((size_t)bo*32 + k)*1024;
            #pragma unroll
            for (int da = 0; da < 4; da++) {
                int a = hi*4 + da;
                float se = 0.f, so = 0.f;
                #pragma unroll
                for (int n = 1; n < 16; n++) {
                    float2 v = V[a*16 + n];            // broadcast
                    float2 e = cs16[(n+15)*16 + lo];   // e^{+2pi i n g/32}
                    float t = v.x*e.x - v.y*e.y;
                    if (n & 1) so += t; else se += t;
                }
                float c0 = bv + V[a*16].x;
                out[base + a*32 + lo     ] = c0 + 2.f*(se + so);
                out[base + a*32 + lo + 16] = c0 + 2.f*(se - so);
            }
        }
    }
}

extern "C" void kernel_launch(void* const* d_in, const int* in_sizes, int n_in,
                              void* d_out, int out_size) {
    const float* x       = (const float*)d_in[0];
    const float* kern    = (const float*)d_in[1];
    const float* bias    = (const float*)d_in[2];
    const float* wig_s2  = (const float*)d_in[3];
    const float* fk_re   = (const float*)d_in[4];
    const float* fk_im   = (const float*)d_in[5];
    const float* wig_so3 = (const float*)d_in[6];
    float* out = (float*)d_out;

    float scaling = 1.0f / sqrtf(32768.0f);

    cudaFuncSetAttribute(k_fz,   cudaFuncAttributeMaxDynamicSharedMemorySize, 65536);
    cudaFuncSetAttribute(k_main, cudaFuncAttributeMaxDynamicSharedMemorySize, 43200);

    k_fhat<<<dim3(16,16), 256>>>(x, wig_s2);
    k_psi <<<256, 256>>>(kern, fk_re, fk_im, scaling);
    k_pack<<<32, 256>>>(wig_so3);
    k_fz  <<<1024, 512, 65536>>>();
    k_main<<<dim3(1024, 4), 256, 43200>>>(bias, out);
}